// round 14
// baseline (speedup 1.0000x reference)
#include <cuda_runtime.h>
#include <cuda_bf16.h>
#include <cuda_fp16.h>
#include <math.h>
#include <stdint.h>

// Problem constants
#define BATCH   2
#define C1      64
#define IN_CH   128
#define OFF_CH  256
#define OUT_CH  64
#define H1      128
#define W1      128
#define H       256
#define W       256
#define HW      (H*W)
#define BN_EPS  1e-5f
#define BN_N    ((float)(BATCH*H*W))

// ---------------- scratch ------------------------------------------------------
__device__ float g_up  [(size_t)BATCH * C1 * HW];
__device__ float g_pre1[(size_t)BATCH * OUT_CH * HW];
__device__ float g_stats[4 * OUT_CH];
__device__ float g_bn   [4 * OUT_CH];

// offsets stored fp16 (NCHW layout)
__device__ __half g_off16[(size_t)BATCH * OFF_CH * HW];

// NHWC fp16 planes ([b][pix][ic], ic contiguous)
__device__ __half g_xc16[(size_t)BATCH * HW * IN_CH];
__device__ __half g_xd16[(size_t)BATCH * HW * IN_CH];
__device__ __half g_p116[(size_t)BATCH * HW * OUT_CH];

// packed fp16 weights [tap][oc][ic]
__device__ __half g_w_off16[9 * OFF_CH * IN_CH];
__device__ __half g_w_c116 [9 * OUT_CH * IN_CH];
__device__ __half g_w_c216 [9 * OUT_CH * OUT_CH];

// ---------------- PTX helpers ----------------------------------------------------
__device__ __forceinline__ uint32_t smem_u32(const void* p) {
    uint32_t a;
    asm("{ .reg .u64 t; cvta.to.shared.u64 t, %1; cvt.u32.u64 %0, t; }"
        : "=r"(a) : "l"(p));
    return a;
}
__device__ __forceinline__ void ldmx4(uint32_t* r, uint32_t a) {
    asm volatile("ldmatrix.sync.aligned.m8n8.x4.shared.b16 {%0,%1,%2,%3}, [%4];"
        : "=r"(r[0]), "=r"(r[1]), "=r"(r[2]), "=r"(r[3]) : "r"(a));
}
__device__ __forceinline__ void ldmx2(uint32_t* r, uint32_t a) {
    asm volatile("ldmatrix.sync.aligned.m8n8.x2.shared.b16 {%0,%1}, [%2];"
        : "=r"(r[0]), "=r"(r[1]) : "r"(a));
}
__device__ __forceinline__ void mma_fp16(float* d, const uint32_t* A, const uint32_t* B) {
    asm volatile(
        "mma.sync.aligned.m16n8k16.row.col.f32.f16.f16.f32 "
        "{%0,%1,%2,%3}, {%4,%5,%6,%7}, {%8,%9}, {%0,%1,%2,%3};"
        : "+f"(d[0]), "+f"(d[1]), "+f"(d[2]), "+f"(d[3])
        : "r"(A[0]), "r"(A[1]), "r"(A[2]), "r"(A[3]), "r"(B[0]), "r"(B[1]));
}
__device__ __forceinline__ void cp_async16(uint32_t dst, const void* src, uint32_t srcsize) {
    asm volatile("cp.async.cg.shared.global [%0], [%1], 16, %2;"
                 :: "r"(dst), "l"(src), "r"(srcsize) : "memory");
}
#define CP_COMMIT() asm volatile("cp.async.commit_group;" ::: "memory")
#define CP_WAIT1()  asm volatile("cp.async.wait_group 1;" ::: "memory")
#define CP_WAIT0()  asm volatile("cp.async.wait_group 0;" ::: "memory")

// ---------------- kernel 1: all weight packs + stats init --------------------------
__global__ void pack_all_kernel(const float* __restrict__ off_w,
                                const float* __restrict__ c1_w,
                                const float* __restrict__ c2_w) {
    const int N0 = 9 * OFF_CH * IN_CH;
    const int N1 = 9 * OUT_CH * IN_CH;
    const int N2 = 9 * OUT_CH * OUT_CH;
    int idx = blockIdx.x * blockDim.x + threadIdx.x;
    if (idx < 256) g_stats[idx] = 0.f;
    if (idx < N0) {
        int ic = idx % IN_CH, rem = idx / IN_CH;
        int oc = rem % OFF_CH, tap = rem / OFF_CH;
        g_w_off16[idx] = __float2half_rn(off_w[((size_t)oc * IN_CH + ic) * 9 + tap]);
    } else if (idx < N0 + N1) {
        int j = idx - N0;
        int ic = j % IN_CH, rem = j / IN_CH;
        int oc = rem % OUT_CH, tap = rem / OUT_CH;
        g_w_c116[j] = __float2half_rn(c1_w[((size_t)oc * IN_CH + ic) * 9 + tap]);
    } else if (idx < N0 + N1 + N2) {
        int j = idx - N0 - N1;
        int ic = j % OUT_CH, rem = j / OUT_CH;
        int oc = rem % OUT_CH, tap = rem / OUT_CH;
        g_w_c216[j] = __float2half_rn(c2_w[((size_t)oc * OUT_CH + ic) * 9 + tap]);
    }
}

// ---------------- kernel 2: fused upsample + concat -> NHWC fp16 -------------------
// cg<2: transpose x2 channels [cg*32, +32). cg>=2: convT compute channels
// 64+(cg-2)*32..+32, writing BOTH g_up (NCHW fp32, gather sources) and xc16.
__global__ void prep_xc_kernel(const float* __restrict__ x1,
                               const float* __restrict__ x2,
                               const float* __restrict__ up_w,
                               const float* __restrict__ up_b) {
    __shared__ float t[32][33];
    __shared__ float ws[64][32][2];    // [ic][o_l][kx] for this block's fixed ky
    __shared__ float xrow[64][16];     // x1 row segment for this pixel strip
    int tx = threadIdx.x, ty = threadIdx.y;
    int tid = ty * 32 + tx;
    int pix0 = blockIdx.x * 32, cg = blockIdx.y, b = blockIdx.z;

    if (cg < 2) {
        #pragma unroll
        for (int i = 0; i < 4; ++i) {
            int c = cg * 32 + ty + i * 8;
            t[ty + i * 8][tx] = x2[((size_t)b * C1 + c) * HW + pix0 + tx];
        }
        __syncthreads();
        #pragma unroll
        for (int i = 0; i < 4; ++i) {
            int pxl = ty + i * 8;
            size_t o = ((size_t)b * HW + pix0 + pxl) * IN_CH + cg * 32 + tx;
            g_xc16[o] = __float2half_rn(t[tx][pxl]);
        }
        return;
    }

    const int o0 = (cg - 2) * 32;
    const int y = pix0 >> 8;                  // all 32 pixels share y
    const int ys = y >> 1, ky = y & 1;
    const int xs0 = (pix0 & 255) >> 1;
    // stage weights (only the 2 kx taps for this ky) and the x1 row segment
    for (int l = tid; l < 64 * 32 * 2; l += 256) {
        int kx = l & 1, ol = (l >> 1) & 31, i = l >> 6;
        ws[i][ol][kx] = up_w[((size_t)i * 64 + o0 + ol) * 4 + ky * 2 + kx];
    }
    for (int l = tid; l < 64 * 16; l += 256) {
        int i = l >> 4, j = l & 15;
        xrow[i][j] = x1[(size_t)(b * C1 + i) * (H1 * W1) + ys * W1 + xs0 + j];
    }
    __syncthreads();

    const int kx = tx & 1;
    const int xj = tx >> 1;
    float acc[4];
    #pragma unroll
    for (int i = 0; i < 4; ++i) acc[i] = up_b[o0 + ty + i * 8];
    #pragma unroll 8
    for (int ic = 0; ic < 64; ++ic) {
        float v = xrow[ic][xj];
        #pragma unroll
        for (int i = 0; i < 4; ++i)
            acc[i] = fmaf(v, ws[ic][ty + i * 8][kx], acc[i]);
    }
    #pragma unroll
    for (int i = 0; i < 4; ++i) {
        int c = o0 + ty + i * 8;
        g_up[((size_t)(b * C1 + c)) * HW + pix0 + tx] = acc[i];
        t[ty + i * 8][tx] = acc[i];
    }
    __syncthreads();
    #pragma unroll
    for (int i = 0; i < 4; ++i) {
        int pxl = ty + i * 8;
        size_t o = ((size_t)b * HW + pix0 + pxl) * IN_CH + C1 + o0 + tx;
        g_xc16[o] = __float2half_rn(t[tx][pxl]);
    }
}

// NCHW fp32 -> NHWC fp16 with BN+ReLU (pre1 path). block (32,8).
__global__ void nchw_to_fp16_kernel(const float* __restrict__ src,
                                    __half* __restrict__ dst, int C,
                                    const float* __restrict__ sc,
                                    const float* __restrict__ sh) {
    __shared__ float t[32][33];
    int tx = threadIdx.x, ty = threadIdx.y;
    int pix0 = blockIdx.x * 32, cg = blockIdx.y * 32, b = blockIdx.z;
    #pragma unroll
    for (int i = 0; i < 4; ++i) {
        int c = cg + ty + i * 8;
        float v = src[((size_t)b * C + c) * HW + pix0 + tx];
        v = fmaxf(fmaf(v, __ldg(sc + c), __ldg(sh + c)), 0.f);
        t[ty + i * 8][tx] = v;
    }
    __syncthreads();
    #pragma unroll
    for (int i = 0; i < 4; ++i) {
        int pxl = ty + i * 8;
        size_t o = ((size_t)b * HW + pix0 + pxl) * C + cg + tx;
        dst[o] = __float2half_rn(t[tx][pxl]);
    }
}

// deformable gather (fp16 offsets) fused with NHWC fp16 transpose. block (32,8).
__global__ void gather_nhwc_kernel(const float* __restrict__ x2) {
    __shared__ float t[32][33];
    int tx = threadIdx.x, ty = threadIdx.y;
    int pix0 = blockIdx.x * 32, cg = blockIdx.y * 32, b = blockIdx.z;
    int pix = pix0 + tx;
    int x = pix & (W - 1), y = pix >> 8;
    const __half* ob = g_off16 + (size_t)b * OFF_CH * HW;
    #pragma unroll
    for (int i = 0; i < 4; ++i) {
        int c = cg + ty + i * 8;
        size_t flat = 2 * ((size_t)c * HW + pix);
        __half2 o2 = *reinterpret_cast<const __half2*>(ob + flat);
        float oy = __half2float(__low2half(o2));
        float ox = __half2float(__high2half(o2));
        float cy = fminf(fmaxf(oy + (float)y, 0.f), (float)(H - 1));
        float cx = fminf(fmaxf(ox + (float)x, 0.f), (float)(W - 1));
        float y0f = floorf(cy), x0f = floorf(cx);
        int y0 = (int)y0f, y1 = (int)ceilf(cy);
        int xx0 = (int)x0f, xx1 = (int)ceilf(cx);
        const float* xp = (c < C1) ? x2 + ((size_t)b * C1 + c) * HW
                                   : g_up + ((size_t)b * C1 + c - C1) * HW;
        float v00 = xp[y0 * W + xx0];
        float v10 = xp[y1 * W + xx0];
        float v01 = xp[y0 * W + xx1];
        float v11 = xp[y1 * W + xx1];
        float wy = cy - y0f, wx = cx - x0f;
        float vt = fmaf(v10 - v00, wy, v00);
        float vb = fmaf(v11 - v01, wy, v01);
        t[ty + i * 8][tx] = fmaf(vb - vt, wx, vt);
    }
    __syncthreads();
    #pragma unroll
    for (int i = 0; i < 4; ++i) {
        int pxl = ty + i * 8;
        size_t o = ((size_t)b * HW + pix0 + pxl) * IN_CH + cg + tx;
        g_xd16[o] = __float2half_rn(t[tx][pxl]);
    }
}

// ---------------- fp16 HMMA conv (R11/R13 config), A-row reuse ---------------------
template <int IC, int MODE>
__global__ __launch_bounds__(128, 2)
void conv_hmma_kernel(const __half* __restrict__ xin,
                      const __half* __restrict__ wgt,
                      int OC,
                      const float* __restrict__ bias, void* __restrict__ outv,
                      float* __restrict__ st_sum, float* __restrict__ st_sq) {
    extern __shared__ __align__(128) char smem[];
    constexpr int NSTAGE = (IC / 64) * 3;
    constexpr int A_SZ  = 130 * 144;
    constexpr int B_TAP = 64 * 144;
    constexpr int SBUF  = A_SZ + 3 * B_TAP;

    const int tid = threadIdx.x, lane = tid & 31, wid = tid >> 5;
    const int wm = wid & 1, wn = wid >> 1;
    const int y  = blockIdx.x >> 1;
    const int x0 = (blockIdx.x & 1) * 128;
    const int b  = blockIdx.z;
    const int oc0 = blockIdx.y * 64;
    const uint32_t sb = smem_u32(smem);
    const __half* xb = xin + (size_t)b * HW * IC;

    float acc[4][4][4];
    #pragma unroll
    for (int mf = 0; mf < 4; ++mf)
        #pragma unroll
        for (int nf = 0; nf < 4; ++nf)
            #pragma unroll
            for (int q = 0; q < 4; ++q) acc[mf][nf][q] = 0.f;

#define FILL(S, BO) do {                                                            \
    const int _s = (S);                                                             \
    const int _icc = (IC == 128) ? (_s / 3) : 0;                                    \
    const int _r   = (IC == 128) ? (_s % 3) : _s;                                   \
    const int _ys = y + _r - 1;                                                     \
    const bool _yok = (_ys >= 0) && (_ys < H);                                      \
    _Pragma("unroll")                                                               \
    for (int _k = 0; _k < 9; ++_k) {                                                \
        int _c = tid + _k * 128;                                                    \
        if (_c < 1040) {                                                            \
            int _px = _c >> 3, _co = _c & 7;                                        \
            int _xs = x0 + _px - 1;                                                 \
            bool _ok = _yok && (_xs >= 0) && (_xs < W);                             \
            size_t _po = _ok ? ((size_t)_ys * W + _xs) * IC : 0;                    \
            cp_async16(sb + (BO) + _px * 144 + _co * 16,                            \
                       (const char*)(xb + _po) + _icc * 128 + _co * 16,             \
                       _ok ? 16u : 0u);                                             \
        }                                                                           \
    }                                                                               \
    _Pragma("unroll")                                                               \
    for (int _k = 0; _k < 12; ++_k) {                                               \
        int _c = tid + _k * 128;                                                    \
        int _t = _c >> 9;                                                           \
        int _rm = _c & 511;                                                         \
        int _row = _rm >> 3, _co = _rm & 7;                                         \
        int _tap = _r * 3 + _t;                                                     \
        cp_async16(sb + (BO) + A_SZ + _t * B_TAP + _row * 144 + _co * 16,           \
                   (const char*)(wgt + (size_t)(_tap * OC + oc0 + _row) * IC        \
                                 + _icc * 64) + _co * 16, 16u);                     \
    }                                                                               \
} while (0)

#define COMPUTE(BO) do {                                                            \
    _Pragma("unroll")                                                               \
    for (int _t = 0; _t < 3; ++_t) {                                                \
        const uint32_t _abase = sb + (BO) + _t * 144;                               \
        const uint32_t _bbase = sb + (BO) + A_SZ + _t * B_TAP;                      \
        _Pragma("unroll")                                                           \
        for (int _ks = 0; _ks < 4; ++_ks) {                                         \
            uint32_t _ah[4][4], _bh[4][2];                                          \
            _Pragma("unroll")                                                       \
            for (int _mf = 0; _mf < 4; ++_mf)                                       \
                ldmx4(_ah[_mf], _abase                                              \
                      + (uint32_t)(wm * 64 + _mf * 16 + (lane & 15)) * 144          \
                      + _ks * 32 + ((lane >> 4) << 4));                             \
            _Pragma("unroll")                                                       \
            for (int _nf = 0; _nf < 4; ++_nf)                                       \
                ldmx2(_bh[_nf], _bbase                                              \
                      + (uint32_t)(wn * 32 + _nf * 8 + (lane & 7)) * 144            \
                      + _ks * 32 + (((lane >> 3) & 1) << 4));                       \
            _Pragma("unroll")                                                       \
            for (int _mf = 0; _mf < 4; ++_mf)                                       \
                _Pragma("unroll")                                                   \
                for (int _nf = 0; _nf < 4; ++_nf)                                   \
                    mma_fp16(acc[_mf][_nf], _ah[_mf], _bh[_nf]);                    \
        }                                                                           \
    }                                                                               \
} while (0)

    FILL(0, 0);
    CP_COMMIT();
    for (int s = 0; s < NSTAGE; ++s) {
        if (s + 1 < NSTAGE) {
            FILL(s + 1, ((s + 1) & 1) * SBUF);
            CP_COMMIT();
            CP_WAIT1();
        } else {
            CP_WAIT0();
        }
        __syncthreads();
        COMPUTE((s & 1) * SBUF);
        __syncthreads();
    }

#undef FILL
#undef COMPUTE

    const int rr0 = lane >> 2, cj = (lane & 3) * 2;

    if (MODE == 0) {
        __half* outb = (__half*)outv + ((size_t)b * OC + oc0) * HW
                       + (size_t)y * W + x0;
        #pragma unroll
        for (int mf = 0; mf < 4; ++mf)
            #pragma unroll
            for (int nf = 0; nf < 4; ++nf)
                #pragma unroll
                for (int q = 0; q < 4; ++q) {
                    int p   = wm * 64 + mf * 16 + rr0 + (q >> 1) * 8;
                    int ocl = wn * 32 + nf * 8 + cj + (q & 1);
                    outb[(size_t)ocl * HW + p] = __float2half_rn(acc[mf][nf][q]);
                }
    } else {
        float* outb = (float*)outv + ((size_t)b * OC + oc0) * HW
                      + (size_t)y * W + x0;
        float ss[8], qq[8];
        #pragma unroll
        for (int i = 0; i < 8; ++i) { ss[i] = 0.f; qq[i] = 0.f; }
        #pragma unroll
        for (int nf = 0; nf < 4; ++nf)
            #pragma unroll
            for (int j = 0; j < 2; ++j) {
                int ocl = wn * 32 + nf * 8 + cj + j;
                float bv = __ldg(bias + oc0 + ocl);
                int idx = nf * 2 + j;
                #pragma unroll
                for (int mf = 0; mf < 4; ++mf)
                    #pragma unroll
                    for (int rr = 0; rr < 2; ++rr) {
                        float v = acc[mf][nf][rr * 2 + j] + bv;
                        int p = wm * 64 + mf * 16 + rr0 + rr * 8;
                        outb[(size_t)ocl * HW + p] = v;
                        ss[idx] += v;
                        qq[idx] += v * v;
                    }
            }
        #pragma unroll
        for (int i = 0; i < 8; ++i) {
            #pragma unroll
            for (int o = 4; o <= 16; o <<= 1) {
                ss[i] += __shfl_xor_sync(0xffffffffu, ss[i], o);
                qq[i] += __shfl_xor_sync(0xffffffffu, qq[i], o);
            }
        }
        if (lane < 4) {
            #pragma unroll
            for (int i = 0; i < 8; ++i) {
                int oc = oc0 + wn * 32 + (i >> 1) * 8 + lane * 2 + (i & 1);
                atomicAdd(&st_sum[oc], ss[i]);
                atomicAdd(&st_sq[oc], qq[i]);
            }
        }
    }
}

// ---------------- BN finalize -----------------------------------------------------
__global__ void bnfin_kernel(const float* __restrict__ sum, const float* __restrict__ sq,
                             const float* __restrict__ g, const float* __restrict__ bb,
                             float* __restrict__ scale, float* __restrict__ shift) {
    int c = threadIdx.x;
    float m = sum[c] / BN_N;
    float v = sq[c] / BN_N - m * m;
    float inv = rsqrtf(v + BN_EPS);
    float sc = g[c] * inv;
    scale[c] = sc;
    shift[c] = bb[c] - m * sc;
}

// ---------------- in-place BN + ReLU on output --------------------------------------
__global__ void final_bnrelu_kernel(float* __restrict__ out,
                                    const float* __restrict__ scale,
                                    const float* __restrict__ shift) {
    size_t idx = (size_t)blockIdx.x * blockDim.x + threadIdx.x;
    if (idx >= (size_t)BATCH * OUT_CH * HW) return;
    int c = (int)(idx >> 16) & (OUT_CH - 1);
    out[idx] = fmaxf(fmaf(out[idx], scale[c], shift[c]), 0.f);
}

// ---------------- launch -------------------------------------------------------------
extern "C" void kernel_launch(void* const* d_in, const int* in_sizes, int n_in,
                              void* d_out, int out_size) {
    const float* x1   = (const float*)d_in[0];
    const float* x2   = (const float*)d_in[1];
    const float* up_w = (const float*)d_in[2];
    const float* up_b = (const float*)d_in[3];
    const float* off_w= (const float*)d_in[4];
    const float* c1_w = (const float*)d_in[5];
    const float* c1_b = (const float*)d_in[6];
    const float* g1   = (const float*)d_in[7];
    const float* b1   = (const float*)d_in[8];
    const float* c2_w = (const float*)d_in[9];
    const float* c2_b = (const float*)d_in[10];
    const float* g2   = (const float*)d_in[11];
    const float* b2   = (const float*)d_in[12];
    float* out = (float*)d_out;

    float *pre1, *stats, *bn;
    __half *off16, *xc16, *xd16, *p116, *w16, *w116, *w216;
    cudaGetSymbolAddress((void**)&pre1,  g_pre1);
    cudaGetSymbolAddress((void**)&stats, g_stats);
    cudaGetSymbolAddress((void**)&bn,    g_bn);
    cudaGetSymbolAddress((void**)&off16, g_off16);
    cudaGetSymbolAddress((void**)&xc16,  g_xc16);
    cudaGetSymbolAddress((void**)&xd16,  g_xd16);
    cudaGetSymbolAddress((void**)&p116,  g_p116);
    cudaGetSymbolAddress((void**)&w16,   g_w_off16);
    cudaGetSymbolAddress((void**)&w116,  g_w_c116);
    cudaGetSymbolAddress((void**)&w216,  g_w_c216);

    float* sum1 = stats;            float* sq1 = stats + 64;
    float* sum2 = stats + 128;      float* sq2 = stats + 192;
    float* sc1 = bn;                float* sh1 = bn + 64;
    float* sc2 = bn + 128;          float* sh2 = bn + 192;

    const int SMEM = 2 * 46368;   // 92736
    cudaFuncSetAttribute(conv_hmma_kernel<IN_CH, 0>,
                         cudaFuncAttributeMaxDynamicSharedMemorySize, SMEM);
    cudaFuncSetAttribute(conv_hmma_kernel<IN_CH, 1>,
                         cudaFuncAttributeMaxDynamicSharedMemorySize, SMEM);
    cudaFuncSetAttribute(conv_hmma_kernel<OUT_CH, 1>,
                         cudaFuncAttributeMaxDynamicSharedMemorySize, SMEM);

    // 1. all weight packs + stats init (one launch)
    {
        int ntot = 9 * OFF_CH * IN_CH + 9 * OUT_CH * IN_CH + 9 * OUT_CH * OUT_CH;
        pack_all_kernel<<<(ntot + 255) / 256, 256>>>(off_w, c1_w, c2_w);
    }
    // 2. fused upsample + concat -> NHWC fp16 (also writes g_up for gather)
    prep_xc_kernel<<<dim3(HW / 32, 4, BATCH), dim3(32, 8)>>>(x1, x2, up_w, up_b);
    // 3. offset conv: (B,128) -> (B,256), fp16 offsets out
    conv_hmma_kernel<IN_CH, 0><<<dim3(512, OFF_CH / 64, BATCH), 128, SMEM>>>(
        xc16, w16, OFF_CH, nullptr, off16, nullptr, nullptr);
    // 4. deformable gather -> NHWC fp16 plane   [PROFILED SLOT]
    gather_nhwc_kernel<<<dim3(HW / 32, IN_CH / 32, BATCH), dim3(32, 8)>>>(x2);
    // 5. conv1: (B,128) -> (B,64), bias + stats
    conv_hmma_kernel<IN_CH, 1><<<dim3(512, 1, BATCH), 128, SMEM>>>(
        xd16, w116, OUT_CH, c1_b, pre1, sum1, sq1);
    // 6. BN1 finalize
    bnfin_kernel<<<1, 64>>>(sum1, sq1, g1, b1, sc1, sh1);
    // 7. pre1 -> BN+ReLU -> NHWC fp16 plane
    nchw_to_fp16_kernel<<<dim3(HW / 32, OUT_CH / 32, BATCH), dim3(32, 8)>>>(
        pre1, p116, OUT_CH, sc1, sh1);
    // 8. conv2: (B,64) -> (B,64), bias + stats
    conv_hmma_kernel<OUT_CH, 1><<<dim3(512, 1, BATCH), 128, SMEM>>>(
        p116, w216, OUT_CH, c2_b, out, sum2, sq2);
    // 9. BN2 finalize
    bnfin_kernel<<<1, 64>>>(sum2, sq2, g2, b2, sc2, sh2);
    // 10. final BN + ReLU
    {
        size_t n = (size_t)BATCH * OUT_CH * HW;
        final_bnrelu_kernel<<<(unsigned)((n + 255) / 256), 256>>>(out, sc2, sh2);
    }
}

// round 15
// speedup vs baseline: 1.1469x; 1.1469x over previous
#include <cuda_runtime.h>
#include <cuda_bf16.h>
#include <cuda_fp16.h>
#include <math.h>
#include <stdint.h>

// Problem constants
#define BATCH   2
#define C1      64
#define IN_CH   128
#define OFF_CH  256
#define OUT_CH  64
#define H1      128
#define W1      128
#define H       256
#define W       256
#define HW      (H*W)
#define BN_EPS  1e-5f
#define BN_N    ((float)(BATCH*H*W))

// ---------------- scratch ------------------------------------------------------
__device__ float g_up  [(size_t)BATCH * C1 * HW];
__device__ float g_stats[4 * OUT_CH];

// offsets stored fp16 (NCHW layout)
__device__ __half g_off16[(size_t)BATCH * OFF_CH * HW];

// NHWC fp16 planes ([b][pix][ic], ic contiguous)
__device__ __half g_xc16[(size_t)BATCH * HW * IN_CH];
__device__ __half g_xd16[(size_t)BATCH * HW * IN_CH];
__device__ __half g_p116[(size_t)BATCH * HW * OUT_CH];

// packed fp16 weights [tap][oc][ic]
__device__ __half g_w_off16[9 * OFF_CH * IN_CH];
__device__ __half g_w_c116 [9 * OUT_CH * IN_CH];
__device__ __half g_w_c216 [9 * OUT_CH * OUT_CH];

// ---------------- PTX helpers ----------------------------------------------------
__device__ __forceinline__ uint32_t smem_u32(const void* p) {
    uint32_t a;
    asm("{ .reg .u64 t; cvta.to.shared.u64 t, %1; cvt.u32.u64 %0, t; }"
        : "=r"(a) : "l"(p));
    return a;
}
__device__ __forceinline__ void ldmx4(uint32_t* r, uint32_t a) {
    asm volatile("ldmatrix.sync.aligned.m8n8.x4.shared.b16 {%0,%1,%2,%3}, [%4];"
        : "=r"(r[0]), "=r"(r[1]), "=r"(r[2]), "=r"(r[3]) : "r"(a));
}
__device__ __forceinline__ void ldmx2(uint32_t* r, uint32_t a) {
    asm volatile("ldmatrix.sync.aligned.m8n8.x2.shared.b16 {%0,%1}, [%2];"
        : "=r"(r[0]), "=r"(r[1]) : "r"(a));
}
__device__ __forceinline__ void mma_fp16(float* d, const uint32_t* A, const uint32_t* B) {
    asm volatile(
        "mma.sync.aligned.m16n8k16.row.col.f32.f16.f16.f32 "
        "{%0,%1,%2,%3}, {%4,%5,%6,%7}, {%8,%9}, {%0,%1,%2,%3};"
        : "+f"(d[0]), "+f"(d[1]), "+f"(d[2]), "+f"(d[3])
        : "r"(A[0]), "r"(A[1]), "r"(A[2]), "r"(A[3]), "r"(B[0]), "r"(B[1]));
}
__device__ __forceinline__ void cp_async16(uint32_t dst, const void* src, uint32_t srcsize) {
    asm volatile("cp.async.cg.shared.global [%0], [%1], 16, %2;"
                 :: "r"(dst), "l"(src), "r"(srcsize) : "memory");
}
#define CP_COMMIT() asm volatile("cp.async.commit_group;" ::: "memory")
#define CP_WAIT1()  asm volatile("cp.async.wait_group 1;" ::: "memory")
#define CP_WAIT0()  asm volatile("cp.async.wait_group 0;" ::: "memory")

// ---------------- kernel 1: all weight packs + stats init --------------------------
__global__ void pack_all_kernel(const float* __restrict__ off_w,
                                const float* __restrict__ c1_w,
                                const float* __restrict__ c2_w) {
    const int N0 = 9 * OFF_CH * IN_CH;
    const int N1 = 9 * OUT_CH * IN_CH;
    const int N2 = 9 * OUT_CH * OUT_CH;
    int idx = blockIdx.x * blockDim.x + threadIdx.x;
    if (idx < 256) g_stats[idx] = 0.f;
    if (idx < N0) {
        int ic = idx % IN_CH, rem = idx / IN_CH;
        int oc = rem % OFF_CH, tap = rem / OFF_CH;
        g_w_off16[idx] = __float2half_rn(off_w[((size_t)oc * IN_CH + ic) * 9 + tap]);
    } else if (idx < N0 + N1) {
        int j = idx - N0;
        int ic = j % IN_CH, rem = j / IN_CH;
        int oc = rem % OUT_CH, tap = rem / OUT_CH;
        g_w_c116[j] = __float2half_rn(c1_w[((size_t)oc * IN_CH + ic) * 9 + tap]);
    } else if (idx < N0 + N1 + N2) {
        int j = idx - N0 - N1;
        int ic = j % OUT_CH, rem = j / OUT_CH;
        int oc = rem % OUT_CH, tap = rem / OUT_CH;
        g_w_c216[j] = __float2half_rn(c2_w[((size_t)oc * OUT_CH + ic) * 9 + tap]);
    }
}

// ---------------- kernel 2: ConvTranspose2d, 2x2 px x 4 oc per thread --------------
__global__ void upcat4_kernel(const float* __restrict__ x1,
                              const float* __restrict__ up_w,
                              const float* __restrict__ up_b) {
    __shared__ float w4[64][4][4];   // [ic][oc_l][k]
    int tid = threadIdx.x;
    int o0 = blockIdx.y * 4, b = blockIdx.z;
    for (int l = tid; l < 64 * 4 * 4; l += 256) {
        int k = l & 3, ol = (l >> 2) & 3, i = l >> 4;
        w4[i][ol][k] = up_w[((size_t)i * 64 + o0 + ol) * 4 + k];
    }
    __syncthreads();
    int pix = blockIdx.x * 256 + tid;
    int ys = pix >> 7, xs = pix & 127;
    float acc[4][4];
    #pragma unroll
    for (int ol = 0; ol < 4; ++ol) {
        float bv = up_b[o0 + ol];
        #pragma unroll
        for (int k = 0; k < 4; ++k) acc[ol][k] = bv;
    }
    const float* xp = x1 + (size_t)b * C1 * H1 * W1 + pix;
    #pragma unroll 4
    for (int i = 0; i < 64; ++i) {
        float v = __ldg(xp + (size_t)i * (H1 * W1));
        #pragma unroll
        for (int ol = 0; ol < 4; ++ol) {
            acc[ol][0] = fmaf(v, w4[i][ol][0], acc[ol][0]);
            acc[ol][1] = fmaf(v, w4[i][ol][1], acc[ol][1]);
            acc[ol][2] = fmaf(v, w4[i][ol][2], acc[ol][2]);
            acc[ol][3] = fmaf(v, w4[i][ol][3], acc[ol][3]);
        }
    }
    #pragma unroll
    for (int ol = 0; ol < 4; ++ol) {
        float* dst = g_up + ((size_t)(b * C1 + o0 + ol) * H + 2 * ys) * W + 2 * xs;
        *(float2*)dst = make_float2(acc[ol][0], acc[ol][1]);
        *(float2*)(dst + W) = make_float2(acc[ol][2], acc[ol][3]);
    }
}

// ---------------- kernel 3: concat (x2 | g_up) -> NHWC fp16. block (32,8) ----------
__global__ void xc_transpose_kernel(const float* __restrict__ x2) {
    __shared__ float t[32][33];
    int tx = threadIdx.x, ty = threadIdx.y;
    int pix0 = blockIdx.x * 32, cg = blockIdx.y * 32, b = blockIdx.z;
    #pragma unroll
    for (int i = 0; i < 4; ++i) {
        int c = cg + ty + i * 8;
        const float* sp = (c < C1) ? x2 + ((size_t)b * C1 + c) * HW
                                   : g_up + ((size_t)b * C1 + c - C1) * HW;
        t[ty + i * 8][tx] = sp[pix0 + tx];
    }
    __syncthreads();
    #pragma unroll
    for (int i = 0; i < 4; ++i) {
        int pxl = ty + i * 8;
        size_t o = ((size_t)b * HW + pix0 + pxl) * IN_CH + cg + tx;
        g_xc16[o] = __float2half_rn(t[tx][pxl]);
    }
}

// ---------------- kernel 5: deformable gather -> NHWC fp16. block (32,8) -----------
__global__ void gather_nhwc_kernel(const float* __restrict__ x2) {
    __shared__ float t[32][33];
    int tx = threadIdx.x, ty = threadIdx.y;
    int pix0 = blockIdx.x * 32, cg = blockIdx.y * 32, b = blockIdx.z;
    int pix = pix0 + tx;
    int x = pix & (W - 1), y = pix >> 8;
    const __half* ob = g_off16 + (size_t)b * OFF_CH * HW;
    #pragma unroll
    for (int i = 0; i < 4; ++i) {
        int c = cg + ty + i * 8;
        size_t flat = 2 * ((size_t)c * HW + pix);
        __half2 o2 = *reinterpret_cast<const __half2*>(ob + flat);
        float oy = __half2float(__low2half(o2));
        float ox = __half2float(__high2half(o2));
        float cy = fminf(fmaxf(oy + (float)y, 0.f), (float)(H - 1));
        float cx = fminf(fmaxf(ox + (float)x, 0.f), (float)(W - 1));
        float y0f = floorf(cy), x0f = floorf(cx);
        int y0 = (int)y0f, y1 = (int)ceilf(cy);
        int xx0 = (int)x0f, xx1 = (int)ceilf(cx);
        const float* xp = (c < C1) ? x2 + ((size_t)b * C1 + c) * HW
                                   : g_up + ((size_t)b * C1 + c - C1) * HW;
        float v00 = xp[y0 * W + xx0];
        float v10 = xp[y1 * W + xx0];
        float v01 = xp[y0 * W + xx1];
        float v11 = xp[y1 * W + xx1];
        float wy = cy - y0f, wx = cx - x0f;
        float vt = fmaf(v10 - v00, wy, v00);
        float vb = fmaf(v11 - v01, wy, v01);
        t[ty + i * 8][tx] = fmaf(vb - vt, wx, vt);
    }
    __syncthreads();
    #pragma unroll
    for (int i = 0; i < 4; ++i) {
        int pxl = ty + i * 8;
        size_t o = ((size_t)b * HW + pix0 + pxl) * IN_CH + cg + tx;
        g_xd16[o] = __float2half_rn(t[tx][pxl]);
    }
}

// ---------------- fp16 HMMA conv, A-row reuse across dx taps -----------------------
// Block: M=128 px x N=64 oc, 4 warps (2m x 2n), warp tile 64x32.
// MODE 0: fp16 NCHW out (offsets). MODE 1: NHWC fp16 out + bias + stats (conv1).
// MODE 2: fp32 NCHW out + bias + stats (conv2).
template <int IC, int MODE>
__global__ __launch_bounds__(128, 2)
void conv_hmma_kernel(const __half* __restrict__ xin,
                      const __half* __restrict__ wgt,
                      int OC,
                      const float* __restrict__ bias, void* __restrict__ outv,
                      float* __restrict__ st_sum, float* __restrict__ st_sq) {
    extern __shared__ __align__(128) char smem[];
    constexpr int NSTAGE = (IC / 64) * 3;
    constexpr int A_SZ  = 130 * 144;
    constexpr int B_TAP = 64 * 144;
    constexpr int SBUF  = A_SZ + 3 * B_TAP;

    const int tid = threadIdx.x, lane = tid & 31, wid = tid >> 5;
    const int wm = wid & 1, wn = wid >> 1;
    const int y  = blockIdx.x >> 1;
    const int x0 = (blockIdx.x & 1) * 128;
    const int b  = blockIdx.z;
    const int oc0 = blockIdx.y * 64;
    const uint32_t sb = smem_u32(smem);
    const __half* xb = xin + (size_t)b * HW * IC;

    float acc[4][4][4];
    #pragma unroll
    for (int mf = 0; mf < 4; ++mf)
        #pragma unroll
        for (int nf = 0; nf < 4; ++nf)
            #pragma unroll
            for (int q = 0; q < 4; ++q) acc[mf][nf][q] = 0.f;

#define FILL(S, BO) do {                                                            \
    const int _s = (S);                                                             \
    const int _icc = (IC == 128) ? (_s / 3) : 0;                                    \
    const int _r   = (IC == 128) ? (_s % 3) : _s;                                   \
    const int _ys = y + _r - 1;                                                     \
    const bool _yok = (_ys >= 0) && (_ys < H);                                      \
    _Pragma("unroll")                                                               \
    for (int _k = 0; _k < 9; ++_k) {                                                \
        int _c = tid + _k * 128;                                                    \
        if (_c < 1040) {                                                            \
            int _px = _c >> 3, _co = _c & 7;                                        \
            int _xs = x0 + _px - 1;                                                 \
            bool _ok = _yok && (_xs >= 0) && (_xs < W);                             \
            size_t _po = _ok ? ((size_t)_ys * W + _xs) * IC : 0;                    \
            cp_async16(sb + (BO) + _px * 144 + _co * 16,                            \
                       (const char*)(xb + _po) + _icc * 128 + _co * 16,             \
                       _ok ? 16u : 0u);                                             \
        }                                                                           \
    }                                                                               \
    _Pragma("unroll")                                                               \
    for (int _k = 0; _k < 12; ++_k) {                                               \
        int _c = tid + _k * 128;                                                    \
        int _t = _c >> 9;                                                           \
        int _rm = _c & 511;                                                         \
        int _row = _rm >> 3, _co = _rm & 7;                                         \
        int _tap = _r * 3 + _t;                                                     \
        cp_async16(sb + (BO) + A_SZ + _t * B_TAP + _row * 144 + _co * 16,           \
                   (const char*)(wgt + (size_t)(_tap * OC + oc0 + _row) * IC        \
                                 + _icc * 64) + _co * 16, 16u);                     \
    }                                                                               \
} while (0)

#define COMPUTE(BO) do {                                                            \
    _Pragma("unroll")                                                               \
    for (int _t = 0; _t < 3; ++_t) {                                                \
        const uint32_t _abase = sb + (BO) + _t * 144;                               \
        const uint32_t _bbase = sb + (BO) + A_SZ + _t * B_TAP;                      \
        _Pragma("unroll")                                                           \
        for (int _ks = 0; _ks < 4; ++_ks) {                                         \
            uint32_t _ah[4][4], _bh[4][2];                                          \
            _Pragma("unroll")                                                       \
            for (int _mf = 0; _mf < 4; ++_mf)                                       \
                ldmx4(_ah[_mf], _abase                                              \
                      + (uint32_t)(wm * 64 + _mf * 16 + (lane & 15)) * 144          \
                      + _ks * 32 + ((lane >> 4) << 4));                             \
            _Pragma("unroll")                                                       \
            for (int _nf = 0; _nf < 4; ++_nf)                                       \
                ldmx2(_bh[_nf], _bbase                                              \
                      + (uint32_t)(wn * 32 + _nf * 8 + (lane & 7)) * 144            \
                      + _ks * 32 + (((lane >> 3) & 1) << 4));                       \
            _Pragma("unroll")                                                       \
            for (int _mf = 0; _mf < 4; ++_mf)                                       \
                _Pragma("unroll")                                                   \
                for (int _nf = 0; _nf < 4; ++_nf)                                   \
                    mma_fp16(acc[_mf][_nf], _ah[_mf], _bh[_nf]);                    \
        }                                                                           \
    }                                                                               \
} while (0)

    FILL(0, 0);
    CP_COMMIT();
    for (int s = 0; s < NSTAGE; ++s) {
        if (s + 1 < NSTAGE) {
            FILL(s + 1, ((s + 1) & 1) * SBUF);
            CP_COMMIT();
            CP_WAIT1();
        } else {
            CP_WAIT0();
        }
        __syncthreads();
        COMPUTE((s & 1) * SBUF);
        __syncthreads();
    }

#undef FILL
#undef COMPUTE

    const int rr0 = lane >> 2, cj = (lane & 3) * 2;

    if (MODE == 0) {
        // fp16 NCHW output (offsets)
        __half* outb = (__half*)outv + ((size_t)b * OC + oc0) * HW
                       + (size_t)y * W + x0;
        #pragma unroll
        for (int mf = 0; mf < 4; ++mf)
            #pragma unroll
            for (int nf = 0; nf < 4; ++nf)
                #pragma unroll
                for (int q = 0; q < 4; ++q) {
                    int p   = wm * 64 + mf * 16 + rr0 + (q >> 1) * 8;
                    int ocl = wn * 32 + nf * 8 + cj + (q & 1);
                    outb[(size_t)ocl * HW + p] = __float2half_rn(acc[mf][nf][q]);
                }
    } else if (MODE == 1) {
        // NHWC fp16 output via smem transpose, + bias + stats
        __half* s16 = (__half*)smem;   // 128 rows x 72-halve stride (18.4 KB)
        float ss[8], qq[8];
        #pragma unroll
        for (int i = 0; i < 8; ++i) { ss[i] = 0.f; qq[i] = 0.f; }
        #pragma unroll
        for (int nf = 0; nf < 4; ++nf)
            #pragma unroll
            for (int j = 0; j < 2; ++j) {
                int ocl = wn * 32 + nf * 8 + cj + j;
                float bv = __ldg(bias + ocl);
                int idx = nf * 2 + j;
                #pragma unroll
                for (int mf = 0; mf < 4; ++mf)
                    #pragma unroll
                    for (int rr = 0; rr < 2; ++rr) {
                        float v = acc[mf][nf][rr * 2 + j] + bv;
                        int p = wm * 64 + mf * 16 + rr0 + rr * 8;
                        s16[p * 72 + ocl] = __float2half_rn(v);
                        ss[idx] += v;
                        qq[idx] += v * v;
                    }
            }
        #pragma unroll
        for (int i = 0; i < 8; ++i) {
            #pragma unroll
            for (int o = 4; o <= 16; o <<= 1) {
                ss[i] += __shfl_xor_sync(0xffffffffu, ss[i], o);
                qq[i] += __shfl_xor_sync(0xffffffffu, qq[i], o);
            }
        }
        if (lane < 4) {
            #pragma unroll
            for (int i = 0; i < 8; ++i) {
                int oc = wn * 32 + (i >> 1) * 8 + lane * 2 + (i & 1);
                atomicAdd(&st_sum[oc], ss[i]);
                atomicAdd(&st_sq[oc], qq[i]);
            }
        }
        __syncthreads();
        // coalesced flat copy: tile is contiguous in NHWC (pixels x0..x0+127)
        uint4* outb4 = (uint4*)((__half*)outv
                       + ((size_t)b * HW + (size_t)y * W + x0) * 64);
        #pragma unroll
        for (int k = 0; k < 8; ++k) {
            int idx = tid + k * 128;           // 1024 uint4 total
            int p = idx >> 3, o8 = (idx & 7) * 8;
            outb4[idx] = *(const uint4*)(s16 + p * 72 + o8);
        }
    } else {
        // fp32 NCHW output + bias + stats (conv2)
        float* outb = (float*)outv + ((size_t)b * OC + oc0) * HW
                      + (size_t)y * W + x0;
        float ss[8], qq[8];
        #pragma unroll
        for (int i = 0; i < 8; ++i) { ss[i] = 0.f; qq[i] = 0.f; }
        #pragma unroll
        for (int nf = 0; nf < 4; ++nf)
            #pragma unroll
            for (int j = 0; j < 2; ++j) {
                int ocl = wn * 32 + nf * 8 + cj + j;
                float bv = __ldg(bias + oc0 + ocl);
                int idx = nf * 2 + j;
                #pragma unroll
                for (int mf = 0; mf < 4; ++mf)
                    #pragma unroll
                    for (int rr = 0; rr < 2; ++rr) {
                        float v = acc[mf][nf][rr * 2 + j] + bv;
                        int p = wm * 64 + mf * 16 + rr0 + rr * 8;
                        outb[(size_t)ocl * HW + p] = v;
                        ss[idx] += v;
                        qq[idx] += v * v;
                    }
            }
        #pragma unroll
        for (int i = 0; i < 8; ++i) {
            #pragma unroll
            for (int o = 4; o <= 16; o <<= 1) {
                ss[i] += __shfl_xor_sync(0xffffffffu, ss[i], o);
                qq[i] += __shfl_xor_sync(0xffffffffu, qq[i], o);
            }
        }
        if (lane < 4) {
            #pragma unroll
            for (int i = 0; i < 8; ++i) {
                int oc = oc0 + wn * 32 + (i >> 1) * 8 + lane * 2 + (i & 1);
                atomicAdd(&st_sum[oc], ss[i]);
                atomicAdd(&st_sq[oc], qq[i]);
            }
        }
    }
}

// ---------------- kernel 7: in-place BN+ReLU on NHWC fp16 plane --------------------
// Computes scale/shift from raw stats per block (no separate finalize launch).
__global__ void bnrelu16_kernel(__half* __restrict__ buf,
                                const float* __restrict__ sum,
                                const float* __restrict__ sq,
                                const float* __restrict__ g,
                                const float* __restrict__ bb) {
    __shared__ float sc[64], sh[64];
    int tid = threadIdx.x;
    if (tid < 64) {
        float m = sum[tid] / BN_N;
        float v = sq[tid] / BN_N - m * m;
        float s = g[tid] * rsqrtf(v + BN_EPS);
        sc[tid] = s;
        sh[tid] = bb[tid] - m * s;
    }
    __syncthreads();
    size_t idx = (size_t)blockIdx.x * 256 + tid;     // uint4 index (8 halves)
    uint4 v4 = ((const uint4*)buf)[idx];
    __half* h = (__half*)&v4;
    int o8 = ((int)idx & 7) * 8;
    #pragma unroll
    for (int i = 0; i < 8; ++i) {
        float v = __half2float(h[i]);
        v = fmaxf(fmaf(v, sc[o8 + i], sh[o8 + i]), 0.f);
        h[i] = __float2half_rn(v);
    }
    ((uint4*)buf)[idx] = v4;
}

// ---------------- kernel 9: final BN+ReLU (fp32 NCHW, in-block finalize) ------------
__global__ void final_bnrelu2_kernel(float* __restrict__ out,
                                     const float* __restrict__ sum,
                                     const float* __restrict__ sq,
                                     const float* __restrict__ g,
                                     const float* __restrict__ bb) {
    __shared__ float sc[64], sh[64];
    int tid = threadIdx.x;
    if (tid < 64) {
        float m = sum[tid] / BN_N;
        float v = sq[tid] / BN_N - m * m;
        float s = g[tid] * rsqrtf(v + BN_EPS);
        sc[tid] = s;
        sh[tid] = bb[tid] - m * s;
    }
    __syncthreads();
    size_t idx = (size_t)blockIdx.x * 256 + tid;     // float4 index
    float4 v4 = ((const float4*)out)[idx];
    int c = (int)((idx * 4) >> 16) & (OUT_CH - 1);   // 65536 floats/channel, 4 | 65536
    v4.x = fmaxf(fmaf(v4.x, sc[c], sh[c]), 0.f);
    v4.y = fmaxf(fmaf(v4.y, sc[c], sh[c]), 0.f);
    v4.z = fmaxf(fmaf(v4.z, sc[c], sh[c]), 0.f);
    v4.w = fmaxf(fmaf(v4.w, sc[c], sh[c]), 0.f);
    ((float4*)out)[idx] = v4;
}

// ---------------- launch -------------------------------------------------------------
extern "C" void kernel_launch(void* const* d_in, const int* in_sizes, int n_in,
                              void* d_out, int out_size) {
    const float* x1   = (const float*)d_in[0];
    const float* x2   = (const float*)d_in[1];
    const float* up_w = (const float*)d_in[2];
    const float* up_b = (const float*)d_in[3];
    const float* off_w= (const float*)d_in[4];
    const float* c1_w = (const float*)d_in[5];
    const float* c1_b = (const float*)d_in[6];
    const float* g1   = (const float*)d_in[7];
    const float* b1   = (const float*)d_in[8];
    const float* c2_w = (const float*)d_in[9];
    const float* c2_b = (const float*)d_in[10];
    const float* g2   = (const float*)d_in[11];
    const float* b2   = (const float*)d_in[12];
    float* out = (float*)d_out;

    float *stats;
    __half *off16, *xc16, *xd16, *p116, *w16, *w116, *w216;
    cudaGetSymbolAddress((void**)&stats, g_stats);
    cudaGetSymbolAddress((void**)&off16, g_off16);
    cudaGetSymbolAddress((void**)&xc16,  g_xc16);
    cudaGetSymbolAddress((void**)&xd16,  g_xd16);
    cudaGetSymbolAddress((void**)&p116,  g_p116);
    cudaGetSymbolAddress((void**)&w16,   g_w_off16);
    cudaGetSymbolAddress((void**)&w116,  g_w_c116);
    cudaGetSymbolAddress((void**)&w216,  g_w_c216);

    float* sum1 = stats;            float* sq1 = stats + 64;
    float* sum2 = stats + 128;      float* sq2 = stats + 192;

    const int SMEM = 2 * 46368;   // 92736
    cudaFuncSetAttribute(conv_hmma_kernel<IN_CH, 0>,
                         cudaFuncAttributeMaxDynamicSharedMemorySize, SMEM);
    cudaFuncSetAttribute(conv_hmma_kernel<IN_CH, 1>,
                         cudaFuncAttributeMaxDynamicSharedMemorySize, SMEM);
    cudaFuncSetAttribute(conv_hmma_kernel<OUT_CH, 2>,
                         cudaFuncAttributeMaxDynamicSharedMemorySize, SMEM);

    // 1. all weight packs + stats init
    {
        int ntot = 9 * OFF_CH * IN_CH + 9 * OUT_CH * IN_CH + 9 * OUT_CH * OUT_CH;
        pack_all_kernel<<<(ntot + 255) / 256, 256>>>(off_w, c1_w, c2_w);
    }
    // 2. conv-transpose upsample
    upcat4_kernel<<<dim3(64, 16, BATCH), 256>>>(x1, up_w, up_b);
    // 3. concat (x2 | up) -> NHWC fp16
    xc_transpose_kernel<<<dim3(HW / 32, IN_CH / 32, BATCH), dim3(32, 8)>>>(x2);
    // 4. offset conv  [PROFILED SLOT]
    conv_hmma_kernel<IN_CH, 0><<<dim3(512, OFF_CH / 64, BATCH), 128, SMEM>>>(
        xc16, w16, OFF_CH, nullptr, off16, nullptr, nullptr);
    // 5. deformable gather -> NHWC fp16
    gather_nhwc_kernel<<<dim3(HW / 32, IN_CH / 32, BATCH), dim3(32, 8)>>>(x2);
    // 6. conv1 -> NHWC fp16 (pre-BN) + stats
    conv_hmma_kernel<IN_CH, 1><<<dim3(512, 1, BATCH), 128, SMEM>>>(
        xd16, w116, OUT_CH, c1_b, p116, sum1, sq1);
    // 7. in-place BN+ReLU on fp16 plane (finalizes stats in-block)
    {
        int n4 = (int)((size_t)BATCH * HW * OUT_CH / 8);   // 1048576 uint4
        bnrelu16_kernel<<<n4 / 256, 256>>>(p116, sum1, sq1, g1, b1);
    }
    // 8. conv2 -> fp32 NCHW + stats
    conv_hmma_kernel<OUT_CH, 2><<<dim3(512, 1, BATCH), 128, SMEM>>>(
        p116, w216, OUT_CH, c2_b, out, sum2, sq2);
    // 9. final BN+ReLU (finalizes stats in-block)
    {
        int n4 = (int)((size_t)BATCH * HW * OUT_CH / 4);   // float4 count
        final_bnrelu2_kernel<<<n4 / 256, 256>>>(out, sum2, sq2, g2, b2);
    }
}

// round 16
// speedup vs baseline: 1.1498x; 1.0025x over previous
#include <cuda_runtime.h>
#include <cuda_bf16.h>
#include <cuda_fp16.h>
#include <math.h>
#include <stdint.h>

// Problem constants
#define BATCH   2
#define C1      64
#define IN_CH   128
#define OFF_CH  256
#define OUT_CH  64
#define H1      128
#define W1      128
#define HW1     (H1*W1)
#define H       256
#define W       256
#define HW      (H*W)
#define BN_EPS  1e-5f
#define BN_N    ((float)(BATCH*H*W))

// ---------------- scratch ------------------------------------------------------
__device__ float g_up  [(size_t)BATCH * C1 * HW];
__device__ float g_stats[4 * OUT_CH];

// offsets stored fp16 (NCHW layout)
__device__ __half g_off16[(size_t)BATCH * OFF_CH * HW];

// NHWC fp16 planes
__device__ __half g_x116[(size_t)BATCH * HW1 * C1];     // x1 transposed
__device__ __half g_xc16[(size_t)BATCH * HW * IN_CH];
__device__ __half g_xd16[(size_t)BATCH * HW * IN_CH];
__device__ __half g_p116[(size_t)BATCH * HW * OUT_CH];

// packed fp16 weights
__device__ __half g_w_off16[9 * OFF_CH * IN_CH];        // [tap][oc][ic]
__device__ __half g_w_c116 [9 * OUT_CH * IN_CH];
__device__ __half g_w_c216 [9 * OUT_CH * OUT_CH];
__device__ __half g_w_up16 [256 * 64];                  // [n=(g,ocl,ph)][ic]

// ---------------- PTX helpers ----------------------------------------------------
__device__ __forceinline__ uint32_t smem_u32(const void* p) {
    uint32_t a;
    asm("{ .reg .u64 t; cvta.to.shared.u64 t, %1; cvt.u32.u64 %0, t; }"
        : "=r"(a) : "l"(p));
    return a;
}
__device__ __forceinline__ void ldmx4(uint32_t* r, uint32_t a) {
    asm volatile("ldmatrix.sync.aligned.m8n8.x4.shared.b16 {%0,%1,%2,%3}, [%4];"
        : "=r"(r[0]), "=r"(r[1]), "=r"(r[2]), "=r"(r[3]) : "r"(a));
}
__device__ __forceinline__ void ldmx2(uint32_t* r, uint32_t a) {
    asm volatile("ldmatrix.sync.aligned.m8n8.x2.shared.b16 {%0,%1}, [%2];"
        : "=r"(r[0]), "=r"(r[1]) : "r"(a));
}
__device__ __forceinline__ void mma_fp16(float* d, const uint32_t* A, const uint32_t* B) {
    asm volatile(
        "mma.sync.aligned.m16n8k16.row.col.f32.f16.f16.f32 "
        "{%0,%1,%2,%3}, {%4,%5,%6,%7}, {%8,%9}, {%0,%1,%2,%3};"
        : "+f"(d[0]), "+f"(d[1]), "+f"(d[2]), "+f"(d[3])
        : "r"(A[0]), "r"(A[1]), "r"(A[2]), "r"(A[3]), "r"(B[0]), "r"(B[1]));
}
__device__ __forceinline__ void cp_async16(uint32_t dst, const void* src, uint32_t srcsize) {
    asm volatile("cp.async.cg.shared.global [%0], [%1], 16, %2;"
                 :: "r"(dst), "l"(src), "r"(srcsize) : "memory");
}
#define CP_COMMIT() asm volatile("cp.async.commit_group;" ::: "memory")
#define CP_WAIT1()  asm volatile("cp.async.wait_group 1;" ::: "memory")
#define CP_WAIT0()  asm volatile("cp.async.wait_group 0;" ::: "memory")

// ---------------- kernel 1: all weight packs + stats init --------------------------
__global__ void pack_all_kernel(const float* __restrict__ off_w,
                                const float* __restrict__ c1_w,
                                const float* __restrict__ c2_w,
                                const float* __restrict__ up_w) {
    const int N0 = 9 * OFF_CH * IN_CH;
    const int N1 = 9 * OUT_CH * IN_CH;
    const int N2 = 9 * OUT_CH * OUT_CH;
    const int N3 = 256 * 64;
    int idx = blockIdx.x * blockDim.x + threadIdx.x;
    if (idx < 256) g_stats[idx] = 0.f;
    if (idx < N0) {
        int ic = idx % IN_CH, rem = idx / IN_CH;
        int oc = rem % OFF_CH, tap = rem / OFF_CH;
        g_w_off16[idx] = __float2half_rn(off_w[((size_t)oc * IN_CH + ic) * 9 + tap]);
    } else if (idx < N0 + N1) {
        int j = idx - N0;
        int ic = j % IN_CH, rem = j / IN_CH;
        int oc = rem % OUT_CH, tap = rem / OUT_CH;
        g_w_c116[j] = __float2half_rn(c1_w[((size_t)oc * IN_CH + ic) * 9 + tap]);
    } else if (idx < N0 + N1 + N2) {
        int j = idx - N0 - N1;
        int ic = j % OUT_CH, rem = j / OUT_CH;
        int oc = rem % OUT_CH, tap = rem / OUT_CH;
        g_w_c216[j] = __float2half_rn(c2_w[((size_t)oc * OUT_CH + ic) * 9 + tap]);
    } else if (idx < N0 + N1 + N2 + N3) {
        int j = idx - N0 - N1 - N2;
        int ic = j & 63;
        int n  = j >> 6;                       // 0..255
        int grp = n >> 6, nl = n & 63;
        int oc = grp * 16 + (nl >> 2);
        int ph = nl & 3;                       // ky*2+kx
        g_w_up16[j] = __float2half_rn(
            up_w[((size_t)(ic * 64 + oc) * 2 + (ph >> 1)) * 2 + (ph & 1)]);
    }
}

// ---------------- kernel 2: x1 NCHW fp32 -> NHWC fp16. block (32,8) ----------------
__global__ void x1_transpose_kernel(const float* __restrict__ x1) {
    __shared__ float t[32][33];
    int tx = threadIdx.x, ty = threadIdx.y;
    int pix0 = blockIdx.x * 32, cg = blockIdx.y * 32, b = blockIdx.z;
    #pragma unroll
    for (int i = 0; i < 4; ++i) {
        int c = cg + ty + i * 8;
        t[ty + i * 8][tx] = x1[((size_t)b * C1 + c) * HW1 + pix0 + tx];
    }
    __syncthreads();
    #pragma unroll
    for (int i = 0; i < 4; ++i) {
        int pxl = ty + i * 8;
        size_t o = ((size_t)b * HW1 + pix0 + pxl) * C1 + cg + tx;
        g_x116[o] = __float2half_rn(t[tx][pxl]);
    }
}

// ---------------- kernel 3: ConvTranspose2d via HMMA GEMM --------------------------
// D[128 src px, 64 n] where n = ocl*4 + (ky*2+kx), oc = grp*16+ocl. One K=64 stage.
// Epilogue scatters to g_up (fp32 NCHW) and xc16 (NHWC, channels 64+oc).
__global__ __launch_bounds__(128)
void upcat_hmma_kernel(const float* __restrict__ up_b) {
    __shared__ __align__(128) char smem[130 * 144 + 64 * 144];
    constexpr int B_OFF = 130 * 144;   // A region padded like conv kernel

    const int tid = threadIdx.x, lane = tid & 31, wid = tid >> 5;
    const int wm = wid & 1, wn = wid >> 1;
    const int ys = blockIdx.x;                    // source row 0..127
    const int grp = blockIdx.y;                   // oc group 0..3
    const int b  = blockIdx.z;
    const uint32_t sb = smem_u32(smem);

    // A fill: 128 src px x 64 ic (row = 128B)
    const __half* xa = g_x116 + ((size_t)b * HW1 + (size_t)ys * W1) * C1;
    #pragma unroll
    for (int k = 0; k < 8; ++k) {
        int c = tid + k * 128;                    // 1024 chunks
        int p = c >> 3, co = c & 7;
        cp_async16(sb + p * 144 + co * 16, (const char*)(xa + (size_t)p * C1) + co * 16, 16u);
    }
    // B fill: 64 n-rows x 64 ic
    const __half* wb = g_w_up16 + (size_t)grp * 64 * 64;
    #pragma unroll
    for (int k = 0; k < 4; ++k) {
        int c = tid + k * 128;                    // 512 chunks
        int row = c >> 3, co = c & 7;
        cp_async16(sb + B_OFF + row * 144 + co * 16,
                   (const char*)(wb + (size_t)row * 64) + co * 16, 16u);
    }
    CP_COMMIT();
    CP_WAIT0();
    __syncthreads();

    float acc[4][4][4];
    #pragma unroll
    for (int mf = 0; mf < 4; ++mf)
        #pragma unroll
        for (int nf = 0; nf < 4; ++nf)
            #pragma unroll
            for (int q = 0; q < 4; ++q) acc[mf][nf][q] = 0.f;

    #pragma unroll
    for (int ks = 0; ks < 4; ++ks) {
        uint32_t ah[4][4], bh[4][2];
        #pragma unroll
        for (int mf = 0; mf < 4; ++mf)
            ldmx4(ah[mf], sb + (uint32_t)(wm * 64 + mf * 16 + (lane & 15)) * 144
                  + ks * 32 + ((lane >> 4) << 4));
        #pragma unroll
        for (int nf = 0; nf < 4; ++nf)
            ldmx2(bh[nf], sb + B_OFF + (uint32_t)(wn * 32 + nf * 8 + (lane & 7)) * 144
                  + ks * 32 + (((lane >> 3) & 1) << 4));
        #pragma unroll
        for (int mf = 0; mf < 4; ++mf)
            #pragma unroll
            for (int nf = 0; nf < 4; ++nf)
                mma_fp16(acc[mf][nf], ah[mf], bh[nf]);
    }

    // epilogue scatter
    const int rr0 = lane >> 2, cj = (lane & 3) * 2;
    #pragma unroll
    for (int nf = 0; nf < 4; ++nf)
        #pragma unroll
        for (int j = 0; j < 2; ++j) {
            int nl = wn * 32 + nf * 8 + cj + j;
            int oc = grp * 16 + (nl >> 2);
            int ky = (nl >> 1) & 1, kx = nl & 1;
            float bv = __ldg(up_b + oc);
            int yd = 2 * ys + ky;
            float* gup = g_up + ((size_t)(b * C1 + oc)) * HW + (size_t)yd * W + kx;
            __half* xcw = g_xc16 + ((size_t)b * HW + (size_t)yd * W + kx) * IN_CH
                          + C1 + oc;
            #pragma unroll
            for (int mf = 0; mf < 4; ++mf)
                #pragma unroll
                for (int rr = 0; rr < 2; ++rr) {
                    float v = acc[mf][nf][rr * 2 + j] + bv;
                    int p = wm * 64 + mf * 16 + rr0 + rr * 8;   // src col
                    gup[2 * p] = v;
                    xcw[(size_t)(2 * p) * IN_CH] = __float2half_rn(v);
                }
        }
}

// ---------------- kernel 4: x2 -> NHWC fp16 (channels 0..63). block (32,8) ---------
__global__ void xc_transpose_kernel(const float* __restrict__ x2) {
    __shared__ float t[32][33];
    int tx = threadIdx.x, ty = threadIdx.y;
    int pix0 = blockIdx.x * 32, cg = blockIdx.y * 32, b = blockIdx.z;
    #pragma unroll
    for (int i = 0; i < 4; ++i) {
        int c = cg + ty + i * 8;
        t[ty + i * 8][tx] = x2[((size_t)b * C1 + c) * HW + pix0 + tx];
    }
    __syncthreads();
    #pragma unroll
    for (int i = 0; i < 4; ++i) {
        int pxl = ty + i * 8;
        size_t o = ((size_t)b * HW + pix0 + pxl) * IN_CH + cg + tx;
        g_xc16[o] = __float2half_rn(t[tx][pxl]);
    }
}

// ---------------- kernel 6: deformable gather -> NHWC fp16. block (32,8) -----------
__global__ void gather_nhwc_kernel(const float* __restrict__ x2) {
    __shared__ float t[32][33];
    int tx = threadIdx.x, ty = threadIdx.y;
    int pix0 = blockIdx.x * 32, cg = blockIdx.y * 32, b = blockIdx.z;
    int pix = pix0 + tx;
    int x = pix & (W - 1), y = pix >> 8;
    const __half* ob = g_off16 + (size_t)b * OFF_CH * HW;
    #pragma unroll
    for (int i = 0; i < 4; ++i) {
        int c = cg + ty + i * 8;
        size_t flat = 2 * ((size_t)c * HW + pix);
        __half2 o2 = *reinterpret_cast<const __half2*>(ob + flat);
        float oy = __half2float(__low2half(o2));
        float ox = __half2float(__high2half(o2));
        float cy = fminf(fmaxf(oy + (float)y, 0.f), (float)(H - 1));
        float cx = fminf(fmaxf(ox + (float)x, 0.f), (float)(W - 1));
        float y0f = floorf(cy), x0f = floorf(cx);
        int y0 = (int)y0f, y1 = (int)ceilf(cy);
        int xx0 = (int)x0f, xx1 = (int)ceilf(cx);
        const float* xp = (c < C1) ? x2 + ((size_t)b * C1 + c) * HW
                                   : g_up + ((size_t)b * C1 + c - C1) * HW;
        float v00 = xp[y0 * W + xx0];
        float v10 = xp[y1 * W + xx0];
        float v01 = xp[y0 * W + xx1];
        float v11 = xp[y1 * W + xx1];
        float wy = cy - y0f, wx = cx - x0f;
        float vt = fmaf(v10 - v00, wy, v00);
        float vb = fmaf(v11 - v01, wy, v01);
        t[ty + i * 8][tx] = fmaf(vb - vt, wx, vt);
    }
    __syncthreads();
    #pragma unroll
    for (int i = 0; i < 4; ++i) {
        int pxl = ty + i * 8;
        size_t o = ((size_t)b * HW + pix0 + pxl) * IN_CH + cg + tx;
        g_xd16[o] = __float2half_rn(t[tx][pxl]);
    }
}

// ---------------- fp16 HMMA conv, A-row reuse across dx taps -----------------------
// MODE 0: fp16 NCHW out. MODE 1: NHWC fp16 out + bias + stats. MODE 2: fp32 NCHW
// out + bias + stats.
template <int IC, int MODE>
__global__ __launch_bounds__(128, 2)
void conv_hmma_kernel(const __half* __restrict__ xin,
                      const __half* __restrict__ wgt,
                      int OC,
                      const float* __restrict__ bias, void* __restrict__ outv,
                      float* __restrict__ st_sum, float* __restrict__ st_sq) {
    extern __shared__ __align__(128) char smem[];
    constexpr int NSTAGE = (IC / 64) * 3;
    constexpr int A_SZ  = 130 * 144;
    constexpr int B_TAP = 64 * 144;
    constexpr int SBUF  = A_SZ + 3 * B_TAP;

    const int tid = threadIdx.x, lane = tid & 31, wid = tid >> 5;
    const int wm = wid & 1, wn = wid >> 1;
    const int y  = blockIdx.x >> 1;
    const int x0 = (blockIdx.x & 1) * 128;
    const int b  = blockIdx.z;
    const int oc0 = blockIdx.y * 64;
    const uint32_t sb = smem_u32(smem);
    const __half* xb = xin + (size_t)b * HW * IC;

    float acc[4][4][4];
    #pragma unroll
    for (int mf = 0; mf < 4; ++mf)
        #pragma unroll
        for (int nf = 0; nf < 4; ++nf)
            #pragma unroll
            for (int q = 0; q < 4; ++q) acc[mf][nf][q] = 0.f;

#define FILL(S, BO) do {                                                            \
    const int _s = (S);                                                             \
    const int _icc = (IC == 128) ? (_s / 3) : 0;                                    \
    const int _r   = (IC == 128) ? (_s % 3) : _s;                                   \
    const int _ys = y + _r - 1;                                                     \
    const bool _yok = (_ys >= 0) && (_ys < H);                                      \
    _Pragma("unroll")                                                               \
    for (int _k = 0; _k < 9; ++_k) {                                                \
        int _c = tid + _k * 128;                                                    \
        if (_c < 1040) {                                                            \
            int _px = _c >> 3, _co = _c & 7;                                        \
            int _xs = x0 + _px - 1;                                                 \
            bool _ok = _yok && (_xs >= 0) && (_xs < W);                             \
            size_t _po = _ok ? ((size_t)_ys * W + _xs) * IC : 0;                    \
            cp_async16(sb + (BO) + _px * 144 + _co * 16,                            \
                       (const char*)(xb + _po) + _icc * 128 + _co * 16,             \
                       _ok ? 16u : 0u);                                             \
        }                                                                           \
    }                                                                               \
    _Pragma("unroll")                                                               \
    for (int _k = 0; _k < 12; ++_k) {                                               \
        int _c = tid + _k * 128;                                                    \
        int _t = _c >> 9;                                                           \
        int _rm = _c & 511;                                                         \
        int _row = _rm >> 3, _co = _rm & 7;                                         \
        int _tap = _r * 3 + _t;                                                     \
        cp_async16(sb + (BO) + A_SZ + _t * B_TAP + _row * 144 + _co * 16,           \
                   (const char*)(wgt + (size_t)(_tap * OC + oc0 + _row) * IC        \
                                 + _icc * 64) + _co * 16, 16u);                     \
    }                                                                               \
} while (0)

#define COMPUTE(BO) do {                                                            \
    _Pragma("unroll")                                                               \
    for (int _t = 0; _t < 3; ++_t) {                                                \
        const uint32_t _abase = sb + (BO) + _t * 144;                               \
        const uint32_t _bbase = sb + (BO) + A_SZ + _t * B_TAP;                      \
        _Pragma("unroll")                                                           \
        for (int _ks = 0; _ks < 4; ++_ks) {                                         \
            uint32_t _ah[4][4], _bh[4][2];                                          \
            _Pragma("unroll")                                                       \
            for (int _mf = 0; _mf < 4; ++_mf)                                       \
                ldmx4(_ah[_mf], _abase                                              \
                      + (uint32_t)(wm * 64 + _mf * 16 + (lane & 15)) * 144          \
                      + _ks * 32 + ((lane >> 4) << 4));                             \
            _Pragma("unroll")                                                       \
            for (int _nf = 0; _nf < 4; ++_nf)                                       \
                ldmx2(_bh[_nf], _bbase                                              \
                      + (uint32_t)(wn * 32 + _nf * 8 + (lane & 7)) * 144            \
                      + _ks * 32 + (((lane >> 3) & 1) << 4));                       \
            _Pragma("unroll")                                                       \
            for (int _mf = 0; _mf < 4; ++_mf)                                       \
                _Pragma("unroll")                                                   \
                for (int _nf = 0; _nf < 4; ++_nf)                                   \
                    mma_fp16(acc[_mf][_nf], _ah[_mf], _bh[_nf]);                    \
        }                                                                           \
    }                                                                               \
} while (0)

    FILL(0, 0);
    CP_COMMIT();
    for (int s = 0; s < NSTAGE; ++s) {
        if (s + 1 < NSTAGE) {
            FILL(s + 1, ((s + 1) & 1) * SBUF);
            CP_COMMIT();
            CP_WAIT1();
        } else {
            CP_WAIT0();
        }
        __syncthreads();
        COMPUTE((s & 1) * SBUF);
        __syncthreads();
    }

#undef FILL
#undef COMPUTE

    const int rr0 = lane >> 2, cj = (lane & 3) * 2;

    if (MODE == 0) {
        __half* outb = (__half*)outv + ((size_t)b * OC + oc0) * HW
                       + (size_t)y * W + x0;
        #pragma unroll
        for (int mf = 0; mf < 4; ++mf)
            #pragma unroll
            for (int nf = 0; nf < 4; ++nf)
                #pragma unroll
                for (int q = 0; q < 4; ++q) {
                    int p   = wm * 64 + mf * 16 + rr0 + (q >> 1) * 8;
                    int ocl = wn * 32 + nf * 8 + cj + (q & 1);
                    outb[(size_t)ocl * HW + p] = __float2half_rn(acc[mf][nf][q]);
                }
    } else if (MODE == 1) {
        __half* s16 = (__half*)smem;
        float ss[8], qq[8];
        #pragma unroll
        for (int i = 0; i < 8; ++i) { ss[i] = 0.f; qq[i] = 0.f; }
        #pragma unroll
        for (int nf = 0; nf < 4; ++nf)
            #pragma unroll
            for (int j = 0; j < 2; ++j) {
                int ocl = wn * 32 + nf * 8 + cj + j;
                float bv = __ldg(bias + ocl);
                int idx = nf * 2 + j;
                #pragma unroll
                for (int mf = 0; mf < 4; ++mf)
                    #pragma unroll
                    for (int rr = 0; rr < 2; ++rr) {
                        float v = acc[mf][nf][rr * 2 + j] + bv;
                        int p = wm * 64 + mf * 16 + rr0 + rr * 8;
                        s16[p * 72 + ocl] = __float2half_rn(v);
                        ss[idx] += v;
                        qq[idx] += v * v;
                    }
            }
        #pragma unroll
        for (int i = 0; i < 8; ++i) {
            #pragma unroll
            for (int o = 4; o <= 16; o <<= 1) {
                ss[i] += __shfl_xor_sync(0xffffffffu, ss[i], o);
                qq[i] += __shfl_xor_sync(0xffffffffu, qq[i], o);
            }
        }
        if (lane < 4) {
            #pragma unroll
            for (int i = 0; i < 8; ++i) {
                int oc = wn * 32 + (i >> 1) * 8 + lane * 2 + (i & 1);
                atomicAdd(&st_sum[oc], ss[i]);
                atomicAdd(&st_sq[oc], qq[i]);
            }
        }
        __syncthreads();
        uint4* outb4 = (uint4*)((__half*)outv
                       + ((size_t)b * HW + (size_t)y * W + x0) * 64);
        #pragma unroll
        for (int k = 0; k < 8; ++k) {
            int idx = tid + k * 128;
            int p = idx >> 3, o8 = (idx & 7) * 8;
            outb4[idx] = *(const uint4*)(s16 + p * 72 + o8);
        }
    } else {
        float* outb = (float*)outv + ((size_t)b * OC + oc0) * HW
                      + (size_t)y * W + x0;
        float ss[8], qq[8];
        #pragma unroll
        for (int i = 0; i < 8; ++i) { ss[i] = 0.f; qq[i] = 0.f; }
        #pragma unroll
        for (int nf = 0; nf < 4; ++nf)
            #pragma unroll
            for (int j = 0; j < 2; ++j) {
                int ocl = wn * 32 + nf * 8 + cj + j;
                float bv = __ldg(bias + oc0 + ocl);
                int idx = nf * 2 + j;
                #pragma unroll
                for (int mf = 0; mf < 4; ++mf)
                    #pragma unroll
                    for (int rr = 0; rr < 2; ++rr) {
                        float v = acc[mf][nf][rr * 2 + j] + bv;
                        int p = wm * 64 + mf * 16 + rr0 + rr * 8;
                        outb[(size_t)ocl * HW + p] = v;
                        ss[idx] += v;
                        qq[idx] += v * v;
                    }
            }
        #pragma unroll
        for (int i = 0; i < 8; ++i) {
            #pragma unroll
            for (int o = 4; o <= 16; o <<= 1) {
                ss[i] += __shfl_xor_sync(0xffffffffu, ss[i], o);
                qq[i] += __shfl_xor_sync(0xffffffffu, qq[i], o);
            }
        }
        if (lane < 4) {
            #pragma unroll
            for (int i = 0; i < 8; ++i) {
                int oc = oc0 + wn * 32 + (i >> 1) * 8 + lane * 2 + (i & 1);
                atomicAdd(&st_sum[oc], ss[i]);
                atomicAdd(&st_sq[oc], qq[i]);
            }
        }
    }
}

// ---------------- in-place BN+ReLU on NHWC fp16 plane (in-block finalize) ----------
__global__ void bnrelu16_kernel(__half* __restrict__ buf,
                                const float* __restrict__ sum,
                                const float* __restrict__ sq,
                                const float* __restrict__ g,
                                const float* __restrict__ bb) {
    __shared__ float sc[64], sh[64];
    int tid = threadIdx.x;
    if (tid < 64) {
        float m = sum[tid] / BN_N;
        float v = sq[tid] / BN_N - m * m;
        float s = g[tid] * rsqrtf(v + BN_EPS);
        sc[tid] = s;
        sh[tid] = bb[tid] - m * s;
    }
    __syncthreads();
    size_t idx = (size_t)blockIdx.x * 256 + tid;
    uint4 v4 = ((const uint4*)buf)[idx];
    __half* h = (__half*)&v4;
    int o8 = ((int)idx & 7) * 8;
    #pragma unroll
    for (int i = 0; i < 8; ++i) {
        float v = __half2float(h[i]);
        v = fmaxf(fmaf(v, sc[o8 + i], sh[o8 + i]), 0.f);
        h[i] = __float2half_rn(v);
    }
    ((uint4*)buf)[idx] = v4;
}

// ---------------- final BN+ReLU (fp32 NCHW, in-block finalize) ----------------------
__global__ void final_bnrelu2_kernel(float* __restrict__ out,
                                     const float* __restrict__ sum,
                                     const float* __restrict__ sq,
                                     const float* __restrict__ g,
                                     const float* __restrict__ bb) {
    __shared__ float sc[64], sh[64];
    int tid = threadIdx.x;
    if (tid < 64) {
        float m = sum[tid] / BN_N;
        float v = sq[tid] / BN_N - m * m;
        float s = g[tid] * rsqrtf(v + BN_EPS);
        sc[tid] = s;
        sh[tid] = bb[tid] - m * s;
    }
    __syncthreads();
    size_t idx = (size_t)blockIdx.x * 256 + tid;
    float4 v4 = ((const float4*)out)[idx];
    int c = (int)((idx * 4) >> 16) & (OUT_CH - 1);
    v4.x = fmaxf(fmaf(v4.x, sc[c], sh[c]), 0.f);
    v4.y = fmaxf(fmaf(v4.y, sc[c], sh[c]), 0.f);
    v4.z = fmaxf(fmaf(v4.z, sc[c], sh[c]), 0.f);
    v4.w = fmaxf(fmaf(v4.w, sc[c], sh[c]), 0.f);
    ((float4*)out)[idx] = v4;
}

// ---------------- launch -------------------------------------------------------------
extern "C" void kernel_launch(void* const* d_in, const int* in_sizes, int n_in,
                              void* d_out, int out_size) {
    const float* x1   = (const float*)d_in[0];
    const float* x2   = (const float*)d_in[1];
    const float* up_w = (const float*)d_in[2];
    const float* up_b = (const float*)d_in[3];
    const float* off_w= (const float*)d_in[4];
    const float* c1_w = (const float*)d_in[5];
    const float* c1_b = (const float*)d_in[6];
    const float* g1   = (const float*)d_in[7];
    const float* b1   = (const float*)d_in[8];
    const float* c2_w = (const float*)d_in[9];
    const float* c2_b = (const float*)d_in[10];
    const float* g2   = (const float*)d_in[11];
    const float* b2   = (const float*)d_in[12];
    float* out = (float*)d_out;

    float *stats;
    __half *off16, *xc16, *xd16, *p116, *w16, *w116, *w216;
    cudaGetSymbolAddress((void**)&stats, g_stats);
    cudaGetSymbolAddress((void**)&off16, g_off16);
    cudaGetSymbolAddress((void**)&xc16,  g_xc16);
    cudaGetSymbolAddress((void**)&xd16,  g_xd16);
    cudaGetSymbolAddress((void**)&p116,  g_p116);
    cudaGetSymbolAddress((void**)&w16,   g_w_off16);
    cudaGetSymbolAddress((void**)&w116,  g_w_c116);
    cudaGetSymbolAddress((void**)&w216,  g_w_c216);

    float* sum1 = stats;            float* sq1 = stats + 64;
    float* sum2 = stats + 128;      float* sq2 = stats + 192;

    const int SMEM = 2 * 46368;
    cudaFuncSetAttribute(conv_hmma_kernel<IN_CH, 0>,
                         cudaFuncAttributeMaxDynamicSharedMemorySize, SMEM);
    cudaFuncSetAttribute(conv_hmma_kernel<IN_CH, 1>,
                         cudaFuncAttributeMaxDynamicSharedMemorySize, SMEM);
    cudaFuncSetAttribute(conv_hmma_kernel<OUT_CH, 2>,
                         cudaFuncAttributeMaxDynamicSharedMemorySize, SMEM);

    // 1. weight packs + stats init
    {
        int ntot = 9 * OFF_CH * IN_CH + 9 * OUT_CH * IN_CH
                 + 9 * OUT_CH * OUT_CH + 256 * 64;
        pack_all_kernel<<<(ntot + 255) / 256, 256>>>(off_w, c1_w, c2_w, up_w);
    }
    // 2. x1 -> NHWC fp16
    x1_transpose_kernel<<<dim3(HW1 / 32, C1 / 32, BATCH), dim3(32, 8)>>>(x1);
    // 3. ConvTranspose via HMMA -> g_up + xc16[64:128]
    upcat_hmma_kernel<<<dim3(H1, 4, BATCH), 128>>>(up_b);
    // 4. x2 -> xc16[0:64]
    xc_transpose_kernel<<<dim3(HW / 32, C1 / 32, BATCH), dim3(32, 8)>>>(x2);
    // 5. offset conv
    conv_hmma_kernel<IN_CH, 0><<<dim3(512, OFF_CH / 64, BATCH), 128, SMEM>>>(
        xc16, w16, OFF_CH, nullptr, off16, nullptr, nullptr);
    // 6. deformable gather -> NHWC fp16
    gather_nhwc_kernel<<<dim3(HW / 32, IN_CH / 32, BATCH), dim3(32, 8)>>>(x2);
    // 7. conv1 -> NHWC fp16 (pre-BN) + stats
    conv_hmma_kernel<IN_CH, 1><<<dim3(512, 1, BATCH), 128, SMEM>>>(
        xd16, w116, OUT_CH, c1_b, p116, sum1, sq1);
    // 8. in-place BN+ReLU on fp16 plane
    {
        int n4 = (int)((size_t)BATCH * HW * OUT_CH / 8);
        bnrelu16_kernel<<<n4 / 256, 256>>>(p116, sum1, sq1, g1, b1);
    }
    // 9. conv2 -> fp32 NCHW + stats
    conv_hmma_kernel<OUT_CH, 2><<<dim3(512, 1, BATCH), 128, SMEM>>>(
        p116, w216, OUT_CH, c2_b, out, sum2, sq2);
    // 10. final BN+ReLU
    {
        int n4 = (int)((size_t)BATCH * HW * OUT_CH / 4);
        final_bnrelu2_kernel<<<n4 / 256, 256>>>(out, sum2, sq2, g2, b2);
    }
}